// round 17
// baseline (speedup 1.0000x reference)
#include <cuda_runtime.h>
#include <cuda_bf16.h>
#include <cuda_fp16.h>
#include <math.h>

// Problem dims (fixed by reference setup_inputs)
#define BB 4
#define TE 512
#define TD 256
#define DM 256
#define TT 4   // t-rows per CTA in score kernel

// Scratch (allocation-free __device__ globals).
// g_EwP: exp(2*enc@W_a) packed as [b][d/2][e] -> half2{d, d+1}. +TE pad for
// prefetch overread.
__device__ __align__(16) __half2 g_EwP[BB * (DM / 2) * TE + TE];
__device__ __align__(16) float   g_Eu[BB * TD * DM];   // exp(2*dec@U_a), f32

__device__ __forceinline__ float frcp(float x) {
    float y; asm("rcp.approx.ftz.f32 %0, %1;" : "=f"(y) : "f"(x)); return y;
}

// ---------------------------------------------------------------------------
// Combined projection GEMM (enc@W_a and dec@U_a in one launch).
// BM=64, BN=64, BK=16, 256 threads, 4x4/thread, double-buffered.
// enc rows -> g_EwP (exp(2x), half2 d-pair-packed, e-contiguous).
// dec rows -> g_Eu (exp(2x), f32, row-major).
// ---------------------------------------------------------------------------
__global__ void __launch_bounds__(256)
proj_gemm2(const float* __restrict__ enc, const float* __restrict__ dec,
           const float* __restrict__ Wa,  const float* __restrict__ Ua) {
    __shared__ float sA[2][16][64];   // sA[p][k][m]
    __shared__ float sB[2][16][64];   // sB[p][k][n]

    const int tid = threadIdx.x;
    const int tx = tid & 15;          // n-sub
    const int ty = tid >> 4;          // m-sub
    const int row0 = blockIdx.x * 64;
    const int n0   = blockIdx.y * 64;

    const bool isW = (row0 < BB * TE);
    const float* X;
    const float* W;
    if (isW) { X = enc + (size_t)row0 * DM;              W = Wa; }
    else     { X = dec + (size_t)(row0 - BB * TE) * DM;  W = Ua; }

    float acc[4][4];
#pragma unroll
    for (int i = 0; i < 4; i++)
#pragma unroll
        for (int j = 0; j < 4; j++) acc[i][j] = 0.f;

    const int lm  = tid >> 2;         // 0..63
    const int lkq = tid & 3;          // 0..3
    const int lr  = tid >> 4;         // 0..15
    const int lc  = tid & 15;         // 0..15

    // prologue: tile 0
    float4 av = *(const float4*)(X + lm * DM + 4 * lkq);
    float4 bv = *(const float4*)(W + lr * DM + n0 + 4 * lc);
    sA[0][4 * lkq + 0][lm] = av.x;
    sA[0][4 * lkq + 1][lm] = av.y;
    sA[0][4 * lkq + 2][lm] = av.z;
    sA[0][4 * lkq + 3][lm] = av.w;
    *(float4*)(&sB[0][lr][4 * lc]) = bv;
    __syncthreads();

    int p = 0;
#pragma unroll 1
    for (int kt = 0; kt < 16; kt++) {
        float4 av2, bv2;
        if (kt < 15) {
            av2 = *(const float4*)(X + lm * DM + (kt + 1) * 16 + 4 * lkq);
            bv2 = *(const float4*)(W + ((kt + 1) * 16 + lr) * DM + n0 + 4 * lc);
        }
#pragma unroll
        for (int kk = 0; kk < 16; kk++) {
            float4 a = *(const float4*)(&sA[p][kk][ty * 4]);
            float4 b = *(const float4*)(&sB[p][kk][tx * 4]);
            acc[0][0] += a.x * b.x; acc[0][1] += a.x * b.y; acc[0][2] += a.x * b.z; acc[0][3] += a.x * b.w;
            acc[1][0] += a.y * b.x; acc[1][1] += a.y * b.y; acc[1][2] += a.y * b.z; acc[1][3] += a.y * b.w;
            acc[2][0] += a.z * b.x; acc[2][1] += a.z * b.y; acc[2][2] += a.z * b.z; acc[2][3] += a.z * b.w;
            acc[3][0] += a.w * b.x; acc[3][1] += a.w * b.y; acc[3][2] += a.w * b.z; acc[3][3] += a.w * b.w;
        }
        if (kt < 15) {
            sA[p ^ 1][4 * lkq + 0][lm] = av2.x;
            sA[p ^ 1][4 * lkq + 1][lm] = av2.y;
            sA[p ^ 1][4 * lkq + 2][lm] = av2.z;
            sA[p ^ 1][4 * lkq + 3][lm] = av2.w;
            *(float4*)(&sB[p ^ 1][lr][4 * lc]) = bv2;
        }
        __syncthreads();
        p ^= 1;
    }

    // Epilogue: exp(2*acc).
    if (isW) {
        // rows are (b, e); cols are d. Store half2{d, d+1} at [b][d/2][e].
        const int b2     = row0 >> 9;            // batch (BM=64 never straddles)
        const int ebase  = (row0 & 511) + ty * 4;
        const int d2base = (n0 + tx * 4) >> 1;   // d-pair index of col 0
#pragma unroll
        for (int i = 0; i < 4; i++) {
            const int e = ebase + i;
            __half2 pA = __floats2half2_rn(__expf(2.f * acc[i][0]),
                                           __expf(2.f * acc[i][1]));
            __half2 pB = __floats2half2_rn(__expf(2.f * acc[i][2]),
                                           __expf(2.f * acc[i][3]));
            g_EwP[((size_t)b2 * (DM / 2) + d2base)     * TE + e] = pA;
            g_EwP[((size_t)b2 * (DM / 2) + d2base + 1) * TE + e] = pB;
        }
    } else {
        float* Y = g_Eu + (size_t)(row0 - BB * TE) * DM;
#pragma unroll
        for (int i = 0; i < 4; i++) {
            float4 o = make_float4(__expf(2.f * acc[i][0]), __expf(2.f * acc[i][1]),
                                   __expf(2.f * acc[i][2]), __expf(2.f * acc[i][3]));
            *(float4*)(Y + (ty * 4 + i) * DM + n0 + tx * 4) = o;
        }
    }
}

// ---------------------------------------------------------------------------
// FUSED kernel: score (exp-identity + paired rcp, SHUFFLE-FREE) -> softmax
// -> context.
//   score'[t,e] = sum_d v'_d / (Ew[e,d]*Eu[t,d] + 1),  v' = -2v
//   (sum_d v_d is const per (b,t) and cancels in softmax).
//   d-pairs share one rcp: v0/d0 + v1/d1 = (v0*d1 + v1*d0)*rcp(d0*d1).
// Grid: 256 CTAs x 512 threads. Warp layout: w&7 -> e-block of 64 (lane owns
// e0=eb+2*lane and e0+1); w>>3 -> d-half (0..127 / 128..255). Each lane
// accumulates its 2 e-rows x 4 t LOCALLY (no shuffles); the two d-halves
// combine via SMEM in Phase C.
// ---------------------------------------------------------------------------
__global__ void __launch_bounds__(512)
attn_score(const float* __restrict__ enc, const float* __restrict__ Va,
           float* __restrict__ out_ctx, float* __restrict__ out_attn) {
    __shared__ __align__(16) float s_eu[TT * DM];          // 4 KB
    __shared__ __align__(16) float s_v[DM];                // 1 KB (holds -2v)
    __shared__ __align__(16) float s_score[TE][TT];        // 8 KB (d-half 0)
    __shared__ __align__(16) float s_part[TE][TT];         // 8 KB (d-half 1)
    __shared__ __align__(16) float s_red[TT * DM];         // 4 KB (Phase D)

    const int b    = blockIdx.x >> 6;
    const int t0   = (blockIdx.x & 63) * TT;
    const int tid  = threadIdx.x;
    const int warp = tid >> 5;
    const int lane = tid & 31;

    // ---- Phase A: stage Eu rows and v' = -2v ----
    {
        if (tid < 256)
            ((float4*)s_eu)[tid] = ((const float4*)(g_Eu + (size_t)(b * TD + t0) * DM))[tid];
        else if (tid < 320) {
            const int i = tid - 256;
            float4 v4 = ((const float4*)Va)[i];
            ((float4*)s_v)[i] = make_float4(-2.f * v4.x, -2.f * v4.y,
                                            -2.f * v4.z, -2.f * v4.w);
        }
    }
    __syncthreads();

    // ---- Phase B: scores, shuffle-free ----
    {
        const int eb = (warp & 7) * 64;   // e-block
        const int dh = warp >> 3;         // d-half: 0 or 1
        const int e0 = eb + 2 * lane;     // lane's first e

        float acc[2][TT];                 // [e-sub][t]
#pragma unroll
        for (int i = 0; i < 2; i++)
#pragma unroll
            for (int t = 0; t < TT; t++) acc[i][t] = 0.f;

        // packed Ew pointer: row d2, column e. Step advances one d-pair row.
        const __half2* wp = g_EwP + ((size_t)b * (DM / 2) + dh * 64) * TE + e0;
        uint2 cur = *(const uint2*)wp;

#pragma unroll 1
        for (int it = 0; it < 64; it++) {
            wp += TE;
            uint2 nxt = *(const uint2*)wp;   // pad overread on final iter

            // cur.x = half2{w(d0,e0), w(d1,e0)}, cur.y = same for e1
            float2 w0 = __half22float2(*(const __half2*)&cur.x);
            float2 w1 = __half22float2(*(const __half2*)&cur.y);

            const int d0 = dh * 128 + 2 * it;
            const float2 v2 = *(const float2*)(s_v + d0);

#pragma unroll
            for (int t = 0; t < TT; t++) {
                const float2 eu2 = *(const float2*)(s_eu + t * DM + d0);
                // e0
                float den0 = fmaf(w0.x, eu2.x, 1.f);
                float den1 = fmaf(w0.y, eu2.y, 1.f);
                float p0   = den0 * den1;
                float n0   = v2.x * den1;
                n0 = fmaf(v2.y, den0, n0);
                acc[0][t] = fmaf(n0, frcp(p0), acc[0][t]);
                // e1
                float den2 = fmaf(w1.x, eu2.x, 1.f);
                float den3 = fmaf(w1.y, eu2.y, 1.f);
                float p1   = den2 * den3;
                float n1   = v2.x * den3;
                n1 = fmaf(v2.y, den2, n1);
                acc[1][t] = fmaf(n1, frcp(p1), acc[1][t]);
            }
            cur = nxt;
        }

        // write local sums (no reduction needed)
        float (*dst)[TT] = (dh == 0) ? s_score : s_part;
        *(float4*)(&dst[e0][0])     = make_float4(acc[0][0], acc[0][1], acc[0][2], acc[0][3]);
        *(float4*)(&dst[e0 + 1][0]) = make_float4(acc[1][0], acc[1][1], acc[1][2], acc[1][3]);
    }
    __syncthreads();

    // ---- Phase C: combine d-halves + softmax (warps 0..3, one t each) ----
    if (warp < TT) {
        const int t = warp;
        float vals[16];
        float mx = -1e30f;
#pragma unroll
        for (int k = 0; k < 16; k++) {
            const int e = lane + 32 * k;
            vals[k] = s_score[e][t] + s_part[e][t];
            mx = fmaxf(mx, vals[k]);
        }
#pragma unroll
        for (int off = 16; off > 0; off >>= 1)
            mx = fmaxf(mx, __shfl_xor_sync(0xffffffffu, mx, off));
        float sum = 0.f;
#pragma unroll
        for (int k = 0; k < 16; k++) {
            vals[k] = exp2f((vals[k] - mx) * 1.4426950408889634f);
            sum += vals[k];
        }
#pragma unroll
        for (int off = 16; off > 0; off >>= 1)
            sum += __shfl_xor_sync(0xffffffffu, sum, off);
        const float inv = 1.0f / sum;
        float* arow = out_attn + ((size_t)(b * TD + t0 + t)) * TE;
#pragma unroll
        for (int k = 0; k < 16; k++) {
            const float w = vals[k] * inv;
            s_score[lane + 32 * k][t] = w;
            arow[lane + 32 * k] = w;
        }
    }
    __syncthreads();

    // ---- Phase D: context = attn @ enc (e-range split across halves) ----
    {
        const int d = tid & 255;
        const int h = tid >> 8;           // 0 or 1: e-half
        const float* encp = enc + (size_t)b * TE * DM + (size_t)h * 256 * DM + d;
        float a0 = 0.f, a1 = 0.f, a2 = 0.f, a3 = 0.f;
#pragma unroll 8
        for (int e = 0; e < 256; e++) {
            const float ev = __ldg(encp + (size_t)e * DM);
            float4 aw = *(const float4*)(&s_score[h * 256 + e][0]);
            a0 = fmaf(aw.x, ev, a0);
            a1 = fmaf(aw.y, ev, a1);
            a2 = fmaf(aw.z, ev, a2);
            a3 = fmaf(aw.w, ev, a3);
        }
        if (h == 1) {
            s_red[0 * 256 + d] = a0;
            s_red[1 * 256 + d] = a1;
            s_red[2 * 256 + d] = a2;
            s_red[3 * 256 + d] = a3;
        }
        __syncthreads();
        if (h == 0) {
            a0 += s_red[0 * 256 + d];
            a1 += s_red[1 * 256 + d];
            a2 += s_red[2 * 256 + d];
            a3 += s_red[3 * 256 + d];
            out_ctx[((size_t)(b * TD + t0 + 0)) * DM + d] = a0;
            out_ctx[((size_t)(b * TD + t0 + 1)) * DM + d] = a1;
            out_ctx[((size_t)(b * TD + t0 + 2)) * DM + d] = a2;
            out_ctx[((size_t)(b * TD + t0 + 3)) * DM + d] = a3;
        }
    }
}

extern "C" void kernel_launch(void* const* d_in, const int* in_sizes, int n_in,
                              void* d_out, int out_size) {
    const float* enc = (const float*)d_in[0];   // [4,512,256]
    const float* dec = (const float*)d_in[1];   // [4,256,256]
    const float* Wa  = (const float*)d_in[2];   // [256,256]
    const float* Ua  = (const float*)d_in[3];   // [256,256]
    const float* Va  = (const float*)d_in[4];   // [256,1]

    float* out      = (float*)d_out;
    float* out_ctx  = out;                          // [4,256,256]
    float* out_attn = out + (size_t)BB * TD * DM;   // [4,256,512]

    // Projections + exp epilogue (Ew packed half2, Eu f32): 192 CTAs
    proj_gemm2<<<dim3((BB * TE + BB * TD) / 64, DM / 64), 256>>>(enc, dec, Wa, Ua);

    // Fused scores + softmax + context: 256 CTAs x 512 threads
    attn_score<<<BB * (TD / TT), 512>>>(enc, Va, out_ctx, out_attn);
}